// round 10
// baseline (speedup 1.0000x reference)
#include <cuda_runtime.h>
#include <cuda_bf16.h>
#include <stdint.h>
#include <float.h>

#define NROWS   65536
#define DIMS    256
#define NCODES  1024
#define TM      128        // rows per block
#define TC      64         // codes per chunk
#define NCHUNK  (NCODES / TC)
#define MARGIN  2e-3f      // R6-proven: ~2.5x bf16 distance-error bound, 0.22 sigma
#define MAXC    3          // per-thread candidate cap
#define ASTRB   528        // bf16 row stride bytes (264 elems) -> conflict-free ldmatrix

// ---- smem layout (bytes) -------------------------------------------------
#define OFF_A      0                         // 128 x 528                 67584
#define OFF_B      67584                     // 64 x 528                  33792
// aliased into B region (only used AFTER the chunk loop):
#define OFF_FMIN   67584                     // i32[128]                    512
#define OFF_BEST   68096                     // u64[128]                   1024
#define OFF_IDX    69120                     // i32[128]                    512
#define OFF_ROVF   69632                     // i32[128]                    512
#define OFF_OVFL   70144                     // i32 count + i32[128]        264
#define OFF_RED    70408                     // double[256]                2048
// persistent:
#define OFF_LIST   101376                    // u64[256][MAXC]             6144
#define OFF_E2     107520                    // f32[1024]                  4096
#define OFF_Z2     111616                    // f32[128]                    512
#define SMEM_BYTES 112128

__device__ float          g_e2[NCODES];
__device__ unsigned short g_ebf[NCODES * DIMS];   // bf16 codebook (pre-converted)
__device__ double         g_loss_accum;

// ---------------------------------------------------------------------------
__device__ __forceinline__ uint32_t smem_u32(const void* p) {
    uint32_t a;
    asm("{ .reg .u64 t; cvta.to.shared.u64 t, %1; cvt.u32.u64 %0, t; }"
        : "=r"(a) : "l"(p));
    return a;
}
__device__ __forceinline__ void ldm_x4(uint32_t* r, uint32_t a) {
    asm volatile("ldmatrix.sync.aligned.m8n8.x4.shared.b16 {%0,%1,%2,%3}, [%4];"
                 : "=r"(r[0]), "=r"(r[1]), "=r"(r[2]), "=r"(r[3]) : "r"(a));
}
__device__ __forceinline__ void mma_bf16(float* c, const uint32_t* a,
                                         const uint32_t* b) {
    asm volatile(
        "mma.sync.aligned.m16n8k16.row.col.f32.bf16.bf16.f32 "
        "{%0,%1,%2,%3},{%4,%5,%6,%7},{%8,%9},{%0,%1,%2,%3};"
        : "+f"(c[0]), "+f"(c[1]), "+f"(c[2]), "+f"(c[3])
        : "r"(a[0]), "r"(a[1]), "r"(a[2]), "r"(a[3]), "r"(b[0]), "r"(b[1]));
}

// ---------------------------------------------------------------------------
// prep: per-code e2 + bf16 codebook + loss zeroing (one warp per code)
// ---------------------------------------------------------------------------
__global__ void vq_prep(const float* __restrict__ emb) {
    if (blockIdx.x == 0 && threadIdx.x == 0) g_loss_accum = 0.0;
    int warp = (blockIdx.x * blockDim.x + threadIdx.x) >> 5;
    int lane = threadIdx.x & 31;
    if (warp < NCODES) {
        const float* row = emb + warp * DIMS;
        float s = 0.f;
#pragma unroll
        for (int i = 0; i < DIMS / 32; i++) {
            float v = row[lane + 32 * i];
            s = __fadd_rn(s, __fmul_rn(v, v));
        }
#pragma unroll
        for (int o = 16; o > 0; o >>= 1)
            s = __fadd_rn(s, __shfl_down_sync(0xffffffffu, s, o));
        if (lane == 0) g_e2[warp] = s;
        // bf16-convert dims lane*8 .. lane*8+7 (16 bytes per lane)
        unsigned short q[8];
#pragma unroll
        for (int j = 0; j < 8; j++) {
            __nv_bfloat16 b = __float2bfloat16_rn(row[lane * 8 + j]);
            q[j] = *(unsigned short*)&b;
        }
        *(uint4*)(g_ebf + (size_t)warp * DIMS + lane * 8) = *(uint4*)q;
    }
}

// stage one 64-code bf16 chunk: pure 16B copy, fully coalesced
__device__ __forceinline__ void stage_B(int chunkBase, char* bt, int tid) {
#pragma unroll
    for (int s = 0; s < 8; s++) {
        int idx = tid + s * 256;     // 0..2047
        int cc  = idx >> 5;          // code row 0..63
        int seg = idx & 31;          // 16B segment
        uint4 v = *(const uint4*)(g_ebf + (size_t)(chunkBase + cc) * DIMS + seg * 8);
        *(uint4*)(bt + (size_t)cc * ASTRB + seg * 16) = v;
    }
}

// canonical exact fp32 distance (R1-proven formula/rounding) + tiebreak pack
__device__ __forceinline__ unsigned long long exact_dist(
    const float* __restrict__ zrow, const float* __restrict__ emb,
    int code, float z2, const float* __restrict__ e2all) {
    const float4* zr = (const float4*)zrow;
    const float4* er = (const float4*)(emb + (size_t)code * DIMS);
    float d0 = 0.f, d1 = 0.f, d2 = 0.f, d3 = 0.f;
#pragma unroll 8
    for (int k4 = 0; k4 < DIMS / 4; k4++) {
        float4 zv = __ldg(&zr[k4]);
        float4 ev = __ldg(&er[k4]);
        d0 = fmaf(zv.x, ev.x, d0);
        d1 = fmaf(zv.y, ev.y, d1);
        d2 = fmaf(zv.z, ev.z, d2);
        d3 = fmaf(zv.w, ev.w, d3);
    }
    float dot  = __fadd_rn(__fadd_rn(d0, d1), __fadd_rn(d2, d3));
    float t    = __fadd_rn(z2, e2all[code]);
    float dist = __fsub_rn(t, __fmul_rn(2.0f, dot));
    return ((unsigned long long)__float_as_uint(dist) << 32) | (unsigned)code;
}

// ---------------------------------------------------------------------------
__global__ void __launch_bounds__(256, 2)
vq_main(const float* __restrict__ z, const float* __restrict__ emb,
        float* __restrict__ out) {
    extern __shared__ char sm[];
    float*  e2s   = (float*)(sm + OFF_E2);
    float*  z2sm  = (float*)(sm + OFF_Z2);
    int*    fminI = (int*)(sm + OFF_FMIN);
    unsigned long long* bestU = (unsigned long long*)(sm + OFF_BEST);
    int*    idxs  = (int*)(sm + OFF_IDX);
    int*    rowOvf= (int*)(sm + OFF_ROVF);
    int*    ovfl  = (int*)(sm + OFF_OVFL);
    double* red   = (double*)(sm + OFF_RED);
    unsigned long long* lst =
        (unsigned long long*)(sm + OFF_LIST) + (size_t)threadIdx.x * MAXC;

    const int tid  = threadIdx.x;
    const int lane = tid & 31;
    const int warp = tid >> 5;
    const int wr   = warp >> 1;          // rows wr*32 .. +31
    const int wc   = warp & 1;           // codes wc*32 .. +31 within chunk
    const int g    = lane >> 2;          // 0..7
    const int colb = (lane & 3) * 2;
    const int rowBase = blockIdx.x * TM;
    const float* zblk = z + (size_t)rowBase * DIMS;
    const uint32_t smb = smem_u32(sm);

    // ---- stage A (z tile, fp32->bf16 once, padded row-major) ----
#pragma unroll 4
    for (int i = tid; i < TM * (DIMS / 4); i += 256) {
        int r  = i >> 6;
        int k4 = i & 63;
        float4 v = __ldg(&((const float4*)zblk)[(size_t)r * (DIMS / 4) + k4]);
        __nv_bfloat162 lo = __float22bfloat162_rn(make_float2(v.x, v.y));
        __nv_bfloat162 hi = __float22bfloat162_rn(make_float2(v.z, v.w));
        uint2 val = make_uint2(*(uint32_t*)&lo, *(uint32_t*)&hi);
        *(uint2*)(sm + OFF_A + (size_t)r * ASTRB + k4 * 8) = val;
    }
    for (int i = tid; i < NCODES; i += 256) e2s[i] = g_e2[i];
    if (tid < TM) {
        const float4* zr = (const float4*)(zblk + (size_t)tid * DIMS);
        float s = 0.f;
        for (int k4 = 0; k4 < DIMS / 4; k4++) {
            float4 v = __ldg(&zr[k4]);
            s = __fadd_rn(s, __fmul_rn(v.x, v.x));
            s = __fadd_rn(s, __fmul_rn(v.y, v.y));
            s = __fadd_rn(s, __fmul_rn(v.z, v.z));
            s = __fadd_rn(s, __fmul_rn(v.w, v.w));
        }
        z2sm[tid] = s;
    }
    __syncthreads();

    // ---- per-lane ldmatrix base addresses (R6-verified mapping) ----
    const uint32_t aBase0 = smb + OFF_A +
        (uint32_t)((wr * 32 + (lane & 15)) * ASTRB) + (lane >> 4) * 16;
    const uint32_t aBase1 = aBase0 + 16 * ASTRB;
    const int brow = (lane & 7) + ((lane & 16) >> 1);
    const uint32_t bBase0 = smb + OFF_B +
        (uint32_t)((wc * 32 + brow) * ASTRB) + ((lane >> 3) & 1) * 16;
    const uint32_t bBase1 = bBase0 + 16 * ASTRB;

    float z2sl[4];
#pragma unroll
    for (int s = 0; s < 4; s++) z2sl[s] = z2sm[wr * 32 + s * 8 + g];

    float rm[4];
#pragma unroll
    for (int s = 0; s < 4; s++) rm[s] = FLT_MAX;
    int cn = 0;
    bool ovfflag = false;

    auto thr_of = [&](int s) -> float {
        float r = (s == 0) ? rm[0] : (s == 1) ? rm[1] : (s == 2) ? rm[2] : rm[3];
        return r + MARGIN;
    };
    auto insert_cand = [&](float da, int tag) {
        if (cn == MAXC) {
            int w = 0;
#pragma unroll
            for (int t = 0; t < MAXC; t++) {
                unsigned long long e = lst[t];
                float v = __uint_as_float((unsigned)(e >> 32));
                int s = ((int)(e & 0xFFFu)) >> 10;
                if (v <= thr_of(s)) lst[w++] = e;
            }
            cn = w;
        }
        if (cn < MAXC)
            lst[cn++] = ((unsigned long long)__float_as_uint(da) << 32) | (unsigned)tag;
        else
            ovfflag = true;
    };

    // ================= chunk loop: bf16 HMMA + slot-min tracking ===========
    for (int c = 0; c < NCHUNK; c++) {
        if (c) __syncthreads();           // prev chunk's B readers done
        stage_B(c * TC, sm + OFF_B, tid);
        __syncthreads();                  // B ready

        float acc[2][4][4];
#pragma unroll
        for (int m = 0; m < 2; m++)
#pragma unroll
            for (int n = 0; n < 4; n++)
#pragma unroll
                for (int e = 0; e < 4; e++) acc[m][n][e] = 0.f;

#pragma unroll
        for (int ks = 0; ks < 16; ks++) {
            const uint32_t ko = ks * 32;
            uint32_t A0[4], A1[4], B01[4], B23[4];
            ldm_x4(A0, aBase0 + ko);
            ldm_x4(A1, aBase1 + ko);
            ldm_x4(B01, bBase0 + ko);
            ldm_x4(B23, bBase1 + ko);
            mma_bf16(acc[0][0], A0, &B01[0]);
            mma_bf16(acc[0][1], A0, &B01[2]);
            mma_bf16(acc[0][2], A0, &B23[0]);
            mma_bf16(acc[0][3], A0, &B23[2]);
            mma_bf16(acc[1][0], A1, &B01[0]);
            mma_bf16(acc[1][1], A1, &B01[2]);
            mma_bf16(acc[1][2], A1, &B23[0]);
            mma_bf16(acc[1][3], A1, &B23[2]);
        }

        // tail: per-slot min first, scan/insert only when within margin
        float t_e2[8];
#pragma unroll
        for (int n = 0; n < 4; n++) {
            t_e2[n * 2]     = e2s[c * TC + wc * 32 + n * 8 + colb];
            t_e2[n * 2 + 1] = e2s[c * TC + wc * 32 + n * 8 + colb + 1];
        }
        const int cBase = c * TC + wc * 32 + colb;
#pragma unroll
        for (int m = 0; m < 2; m++)
#pragma unroll
            for (int eh = 0; eh < 2; eh++) {
                const int slot = m * 2 + eh;
                float z2e = z2sl[slot];
                float kv[8];
                float smin = FLT_MAX;
#pragma unroll
                for (int n = 0; n < 4; n++) {
#pragma unroll
                    for (int el = 0; el < 2; el++) {
                        float da = fmaf(-2.f, acc[m][n][eh * 2 + el],
                                        z2e + t_e2[n * 2 + el]);
                        kv[n * 2 + el] = da;
                        smin = fminf(smin, da);
                    }
                }
                float rnew = fminf(rm[slot], smin);
                if (smin <= rnew + MARGIN) {
#pragma unroll
                    for (int q = 0; q < 8; q++)
                        if (kv[q] <= rnew + MARGIN) {
                            int code = cBase + (q >> 1) * 8 + (q & 1);
                            insert_cand(kv[q], (slot << 10) | code);
                        }
                }
                rm[slot] = rnew;
            }
    }
    __syncthreads();                      // chunk loop done; B region reusable

    // ---- init aliased post-loop state ----
    if (tid < TM) {
        fminI[tid]  = 0x7f800000;
        bestU[tid]  = ~0ull;
        rowOvf[tid] = 0;
    }
    if (tid == 0) ovfl[0] = 0;
    __syncthreads();

#pragma unroll
    for (int s = 0; s < 4; s++)
        atomicMin(&fminI[wr * 32 + s * 8 + g], __float_as_int(rm[s]));
    if (ovfflag)
#pragma unroll
        for (int s = 0; s < 4; s++) rowOvf[wr * 32 + s * 8 + g] = 1;
    __syncthreads();

    // ---- exact rescore of surviving candidates (canonical formula) ----
    for (int t = 0; t < cn; t++) {
        unsigned long long e = lst[t];
        float v  = __uint_as_float((unsigned)(e >> 32));
        int tag  = (int)(e & 0xFFFu);
        int s    = tag >> 10;
        int code = tag & 1023;
        int row  = wr * 32 + s * 8 + g;
        if (v <= __int_as_float(fminI[row]) + MARGIN) {
            unsigned long long p =
                exact_dist(zblk + (size_t)row * DIMS, emb, code, z2sm[row], e2s);
            atomicMin(&bestU[row], p);
        }
    }
    __syncthreads();

    // ---- overflow rows: full exact scan (safety net, ~never taken) ----
    if (tid < TM && rowOvf[tid]) {
        int p = atomicAdd(&ovfl[0], 1);
        ovfl[1 + p] = tid;
    }
    __syncthreads();
    int novf = ovfl[0];
    for (int f = 0; f < novf; f++) {
        int row = ovfl[1 + f];
        float z2r = z2sm[row];
        for (int code = tid; code < NCODES; code += 256) {
            unsigned long long p =
                exact_dist(zblk + (size_t)row * DIMS, emb, code, z2r, e2s);
            atomicMin(&bestU[row], p);
        }
    }
    if (novf) __syncthreads();

    if (tid < TM) idxs[tid] = (int)(bestU[tid] & 0xffffffffull);
    __syncthreads();

    // ================= epilogue: gather / STE / loss ======================
    double lsum = 0.0;
    float* outblk = out + (size_t)rowBase * DIMS;
#pragma unroll 4
    for (int i = tid; i < TM * (DIMS / 4); i += 256) {
        int r  = i >> 6;
        int k4 = i & 63;
        float4 zv = __ldg(&((const float4*)zblk)[(size_t)r * (DIMS / 4) + k4]);
        float4 qv = __ldg(&((const float4*)(emb + (size_t)idxs[r] * DIMS))[k4]);
        float4 ov; float d;
        d = __fsub_rn(qv.x, zv.x); ov.x = __fadd_rn(zv.x, d); lsum += (double)__fmul_rn(d, d);
        d = __fsub_rn(qv.y, zv.y); ov.y = __fadd_rn(zv.y, d); lsum += (double)__fmul_rn(d, d);
        d = __fsub_rn(qv.z, zv.z); ov.z = __fadd_rn(zv.z, d); lsum += (double)__fmul_rn(d, d);
        d = __fsub_rn(qv.w, zv.w); ov.w = __fadd_rn(zv.w, d); lsum += (double)__fmul_rn(d, d);
        ((float4*)outblk)[i] = ov;
    }
    red[tid] = lsum;
    __syncthreads();
    for (int s = 128; s > 0; s >>= 1) {
        if (tid < s) red[tid] += red[tid + s];
        __syncthreads();
    }
    if (tid == 0) atomicAdd(&g_loss_accum, red[0]);
}

// ---------------------------------------------------------------------------
__global__ void vq_finalize(float* __restrict__ out, int out_size) {
    double mean = g_loss_accum / (double)((size_t)NROWS * DIMS);
    float loss = (float)(0.5 * mean);
    out[out_size - 2] = loss;   // commitment_loss
    out[out_size - 1] = loss;   // emb_loss
}

// ---------------------------------------------------------------------------
extern "C" void kernel_launch(void* const* d_in, const int* in_sizes, int n_in,
                              void* d_out, int out_size) {
    const float* z   = (const float*)d_in[0];
    const float* emb = (const float*)d_in[1];
    if (n_in >= 2 && in_sizes[0] == NCODES * DIMS && in_sizes[1] == NROWS * DIMS) {
        emb = (const float*)d_in[0];
        z   = (const float*)d_in[1];
    }
    float* out = (float*)d_out;

    vq_prep<<<(NCODES * 32 + 255) / 256, 256>>>(emb);

    cudaFuncSetAttribute(vq_main, cudaFuncAttributeMaxDynamicSharedMemorySize,
                         SMEM_BYTES);
    vq_main<<<NROWS / TM, 256, SMEM_BYTES>>>(z, emb, out);

    vq_finalize<<<1, 1>>>(out, out_size);
}

// round 11
// speedup vs baseline: 43.4307x; 43.4307x over previous
#include <cuda_runtime.h>
#include <cuda_bf16.h>
#include <stdint.h>
#include <float.h>

#define NROWS   65536
#define DIMS    256
#define NCODES  1024
#define TM      128        // rows per block
#define TC      64         // codes per chunk
#define NCHUNK  (NCODES / TC)
#define MARGIN  2e-3f      // R6-proven: ~2.5x bf16 distance-error bound, 0.22 sigma
#define ASTRB   528        // bf16 row stride bytes -> conflict-free ldmatrix

// ---- smem layout (bytes) -------------------------------------------------
#define OFF_A      0                         // 128 x 528                 67584
#define OFF_B      67584                     // 64 x 528                  33792
// aliased into B region (only used AFTER the chunk loop):
#define OFF_FMIN   67584                     // i32[128]                    512
#define OFF_BEST   68096                     // u64[128]                   1024
#define OFF_IDX    69120                     // i32[128]                    512
#define OFF_ROVF   69632                     // i32[128]                    512
#define OFF_OVFL   70144                     // i32 count + i32[128]        520
#define OFF_RED    70664                     // double[256]                2048
// persistent:
#define OFF_E2     101376                    // f32[1024]                  4096
#define OFF_Z2     105472                    // f32[128]                    512
#define SMEM_BYTES 105984

__device__ float          g_e2[NCODES];
__device__ unsigned short g_ebf[NCODES * DIMS];   // bf16 codebook (pre-converted)
__device__ double         g_loss_accum;

// ---------------------------------------------------------------------------
__device__ __forceinline__ uint32_t smem_u32(const void* p) {
    uint32_t a;
    asm("{ .reg .u64 t; cvta.to.shared.u64 t, %1; cvt.u32.u64 %0, t; }"
        : "=r"(a) : "l"(p));
    return a;
}
__device__ __forceinline__ void ldm_x4(uint32_t* r, uint32_t a) {
    asm volatile("ldmatrix.sync.aligned.m8n8.x4.shared.b16 {%0,%1,%2,%3}, [%4];"
                 : "=r"(r[0]), "=r"(r[1]), "=r"(r[2]), "=r"(r[3]) : "r"(a));
}
__device__ __forceinline__ void mma_bf16(float* c, const uint32_t* a,
                                         const uint32_t* b) {
    asm volatile(
        "mma.sync.aligned.m16n8k16.row.col.f32.bf16.bf16.f32 "
        "{%0,%1,%2,%3},{%4,%5,%6,%7},{%8,%9},{%0,%1,%2,%3};"
        : "+f"(c[0]), "+f"(c[1]), "+f"(c[2]), "+f"(c[3])
        : "r"(a[0]), "r"(a[1]), "r"(a[2]), "r"(a[3]), "r"(b[0]), "r"(b[1]));
}

// ---------------------------------------------------------------------------
// prep: per-code e2 + bf16 codebook + loss zeroing (one warp per code)
// ---------------------------------------------------------------------------
__global__ void vq_prep(const float* __restrict__ emb) {
    if (blockIdx.x == 0 && threadIdx.x == 0) g_loss_accum = 0.0;
    int warp = (blockIdx.x * blockDim.x + threadIdx.x) >> 5;
    int lane = threadIdx.x & 31;
    if (warp < NCODES) {
        const float* row = emb + warp * DIMS;
        float s = 0.f;
#pragma unroll
        for (int i = 0; i < DIMS / 32; i++) {
            float v = row[lane + 32 * i];
            s = __fadd_rn(s, __fmul_rn(v, v));
        }
#pragma unroll
        for (int o = 16; o > 0; o >>= 1)
            s = __fadd_rn(s, __shfl_down_sync(0xffffffffu, s, o));
        if (lane == 0) g_e2[warp] = s;
        unsigned short q[8];
#pragma unroll
        for (int j = 0; j < 8; j++) {
            __nv_bfloat16 b = __float2bfloat16_rn(row[lane * 8 + j]);
            q[j] = *(unsigned short*)&b;
        }
        *(uint4*)(g_ebf + (size_t)warp * DIMS + lane * 8) = *(uint4*)q;
    }
}

// stage one 64-code bf16 chunk: pure 16B copy, fully coalesced
__device__ __forceinline__ void stage_B(int chunkBase, char* bt, int tid) {
#pragma unroll
    for (int s = 0; s < 8; s++) {
        int idx = tid + s * 256;
        int cc  = idx >> 5;
        int seg = idx & 31;
        uint4 v = *(const uint4*)(g_ebf + (size_t)(chunkBase + cc) * DIMS + seg * 8);
        *(uint4*)(bt + (size_t)cc * ASTRB + seg * 16) = v;
    }
}

// canonical exact fp32 distance (R1-proven formula/rounding) + tiebreak pack
__device__ __forceinline__ unsigned long long exact_dist(
    const float* __restrict__ zrow, const float* __restrict__ emb,
    int code, float z2, const float* __restrict__ e2all) {
    const float4* zr = (const float4*)zrow;
    const float4* er = (const float4*)(emb + (size_t)code * DIMS);
    float d0 = 0.f, d1 = 0.f, d2 = 0.f, d3 = 0.f;
#pragma unroll 8
    for (int k4 = 0; k4 < DIMS / 4; k4++) {
        float4 zv = __ldg(&zr[k4]);
        float4 ev = __ldg(&er[k4]);
        d0 = fmaf(zv.x, ev.x, d0);
        d1 = fmaf(zv.y, ev.y, d1);
        d2 = fmaf(zv.z, ev.z, d2);
        d3 = fmaf(zv.w, ev.w, d3);
    }
    float dot  = __fadd_rn(__fadd_rn(d0, d1), __fadd_rn(d2, d3));
    float t    = __fadd_rn(z2, e2all[code]);
    float dist = __fsub_rn(t, __fmul_rn(2.0f, dot));
    return ((unsigned long long)__float_as_uint(dist) << 32) | (unsigned)code;
}

// ---------------------------------------------------------------------------
__global__ void __launch_bounds__(256, 2)
vq_main(const float* __restrict__ z, const float* __restrict__ emb,
        float* __restrict__ out) {
    extern __shared__ char sm[];
    float*  e2s   = (float*)(sm + OFF_E2);
    float*  z2sm  = (float*)(sm + OFF_Z2);
    int*    fminI = (int*)(sm + OFF_FMIN);
    unsigned long long* bestU = (unsigned long long*)(sm + OFF_BEST);
    int*    idxs  = (int*)(sm + OFF_IDX);
    int*    rowOvf= (int*)(sm + OFF_ROVF);
    int*    ovfl  = (int*)(sm + OFF_OVFL);
    double* red   = (double*)(sm + OFF_RED);

    const int tid  = threadIdx.x;
    const int lane = tid & 31;
    const int warp = tid >> 5;
    const int wr   = warp >> 1;          // rows wr*32 .. +31
    const int wc   = warp & 1;           // codes wc*32 .. +31 within chunk
    const int g    = lane >> 2;          // 0..7
    const int colb = (lane & 3) * 2;
    const int rowBase = blockIdx.x * TM;
    const float* zblk = z + (size_t)rowBase * DIMS;
    const uint32_t smb = smem_u32(sm);

    // ---- stage A (z tile, fp32->bf16 once, padded row-major) ----
#pragma unroll 4
    for (int i = tid; i < TM * (DIMS / 4); i += 256) {
        int r  = i >> 6;
        int k4 = i & 63;
        float4 v = __ldg(&((const float4*)zblk)[(size_t)r * (DIMS / 4) + k4]);
        __nv_bfloat162 lo = __float22bfloat162_rn(make_float2(v.x, v.y));
        __nv_bfloat162 hi = __float22bfloat162_rn(make_float2(v.z, v.w));
        uint2 val = make_uint2(*(uint32_t*)&lo, *(uint32_t*)&hi);
        *(uint2*)(sm + OFF_A + (size_t)r * ASTRB + k4 * 8) = val;
    }
    for (int i = tid; i < NCODES; i += 256) e2s[i] = g_e2[i];
    if (tid < TM) {
        const float4* zr = (const float4*)(zblk + (size_t)tid * DIMS);
        float s = 0.f;
        for (int k4 = 0; k4 < DIMS / 4; k4++) {
            float4 v = __ldg(&zr[k4]);
            s = __fadd_rn(s, __fmul_rn(v.x, v.x));
            s = __fadd_rn(s, __fmul_rn(v.y, v.y));
            s = __fadd_rn(s, __fmul_rn(v.z, v.z));
            s = __fadd_rn(s, __fmul_rn(v.w, v.w));
        }
        z2sm[tid] = s;
    }
    __syncthreads();

    // ---- per-lane ldmatrix base addresses (R6-verified mapping) ----
    const uint32_t aBase0 = smb + OFF_A +
        (uint32_t)((wr * 32 + (lane & 15)) * ASTRB) + (lane >> 4) * 16;
    const uint32_t aBase1 = aBase0 + 16 * ASTRB;
    const int brow = (lane & 7) + ((lane & 16) >> 1);
    const uint32_t bBase0 = smb + OFF_B +
        (uint32_t)((wc * 32 + brow) * ASTRB) + ((lane >> 3) & 1) * 16;
    const uint32_t bBase1 = bBase0 + 16 * ASTRB;

    float z2sl[4];
#pragma unroll
    for (int s = 0; s < 4; s++) z2sl[s] = z2sm[wr * 32 + s * 8 + g];

    // per-slot top-3 tracking (values; codes for top-2)
    float b1[4], b2[4], b3[4];
    int   c1[4], c2[4];
#pragma unroll
    for (int s = 0; s < 4; s++) {
        b1[s] = FLT_MAX; b2[s] = FLT_MAX; b3[s] = FLT_MAX;
        c1[s] = 0; c2[s] = 0;
    }

    // ================= chunk loop: bf16 HMMA + top-3 tracking ==============
    for (int c = 0; c < NCHUNK; c++) {
        if (c) __syncthreads();           // prev chunk's B readers done
        stage_B(c * TC, sm + OFF_B, tid);
        __syncthreads();                  // B ready

        float acc[2][4][4];
#pragma unroll
        for (int m = 0; m < 2; m++)
#pragma unroll
            for (int n = 0; n < 4; n++)
#pragma unroll
                for (int e = 0; e < 4; e++) acc[m][n][e] = 0.f;

#pragma unroll
        for (int ks = 0; ks < 16; ks++) {
            const uint32_t ko = ks * 32;
            uint32_t A0[4], A1[4], B01[4], B23[4];
            ldm_x4(A0, aBase0 + ko);
            ldm_x4(A1, aBase1 + ko);
            ldm_x4(B01, bBase0 + ko);
            ldm_x4(B23, bBase1 + ko);
            mma_bf16(acc[0][0], A0, &B01[0]);
            mma_bf16(acc[0][1], A0, &B01[2]);
            mma_bf16(acc[0][2], A0, &B23[0]);
            mma_bf16(acc[0][3], A0, &B23[2]);
            mma_bf16(acc[1][0], A1, &B01[0]);
            mma_bf16(acc[1][1], A1, &B01[2]);
            mma_bf16(acc[1][2], A1, &B23[0]);
            mma_bf16(acc[1][3], A1, &B23[2]);
        }

        // tail: distances, slot min, rare top-3 update (skip if smin >= b3)
        float t_e2[8];
#pragma unroll
        for (int n = 0; n < 4; n++) {
            t_e2[n * 2]     = e2s[c * TC + wc * 32 + n * 8 + colb];
            t_e2[n * 2 + 1] = e2s[c * TC + wc * 32 + n * 8 + colb + 1];
        }
        const int cBase = c * TC + wc * 32 + colb;
#pragma unroll
        for (int m = 0; m < 2; m++)
#pragma unroll
            for (int eh = 0; eh < 2; eh++) {
                const int slot = m * 2 + eh;
                const float z2e = z2sl[slot];
                float kv[8];
                float smin = FLT_MAX;
#pragma unroll
                for (int n = 0; n < 4; n++)
#pragma unroll
                    for (int el = 0; el < 2; el++) {
                        float da = fmaf(-2.f, acc[m][n][eh * 2 + el],
                                        z2e + t_e2[n * 2 + el]);
                        kv[n * 2 + el] = da;
                        smin = fminf(smin, da);
                    }
                if (smin < b3[slot]) {
#pragma unroll
                    for (int q = 0; q < 8; q++) {
                        float v = kv[q];
                        int   code = cBase + (q >> 1) * 8 + (q & 1);
                        if (v < b1[slot]) {
                            b3[slot] = b2[slot];
                            b2[slot] = b1[slot]; c2[slot] = c1[slot];
                            b1[slot] = v;        c1[slot] = code;
                        } else if (v < b2[slot]) {
                            b3[slot] = b2[slot];
                            b2[slot] = v;        c2[slot] = code;
                        } else if (v < b3[slot]) {
                            b3[slot] = v;
                        }
                    }
                }
            }
    }
    __syncthreads();                      // chunk loop done; B region reusable

    // ---- init aliased post-loop state ----
    if (tid < TM) {
        fminI[tid]  = 0x7f800000;
        bestU[tid]  = ~0ull;
        rowOvf[tid] = 0;
    }
    if (tid == 0) ovfl[0] = 0;
    __syncthreads();

#pragma unroll
    for (int s = 0; s < 4; s++)
        atomicMin(&fminI[wr * 32 + s * 8 + g], __float_as_int(b1[s]));
    __syncthreads();

    // ---- rescore top-2 candidates; flag rows needing full scan ----
#pragma unroll
    for (int s = 0; s < 4; s++) {
        const int row = wr * 32 + s * 8 + g;
        const float thr = __int_as_float(fminI[row]) + MARGIN;
        if (b1[s] <= thr)
            atomicMin(&bestU[row],
                      exact_dist(zblk + (size_t)row * DIMS, emb, c1[s],
                                 z2sm[row], e2s));
        if (b2[s] <= thr)
            atomicMin(&bestU[row],
                      exact_dist(zblk + (size_t)row * DIMS, emb, c2[s],
                                 z2sm[row], e2s));
        if (b3[s] <= thr) rowOvf[row] = 1;
    }
    __syncthreads();

    // ---- overflow rows: full exact scan (safety net, ~never taken) ----
    if (tid < TM && rowOvf[tid]) {
        int p = atomicAdd(&ovfl[0], 1);
        ovfl[1 + p] = tid;
    }
    __syncthreads();
    int novf = ovfl[0];
    for (int f = 0; f < novf; f++) {
        int row = ovfl[1 + f];
        float z2r = z2sm[row];
        for (int code = tid; code < NCODES; code += 256) {
            unsigned long long p =
                exact_dist(zblk + (size_t)row * DIMS, emb, code, z2r, e2s);
            atomicMin(&bestU[row], p);
        }
    }
    if (novf) __syncthreads();

    if (tid < TM) idxs[tid] = (int)(bestU[tid] & 0xffffffffull);
    __syncthreads();

    // ================= epilogue: gather / STE / loss ======================
    double lsum = 0.0;
    float* outblk = out + (size_t)rowBase * DIMS;
#pragma unroll 4
    for (int i = tid; i < TM * (DIMS / 4); i += 256) {
        int r  = i >> 6;
        int k4 = i & 63;
        float4 zv = __ldg(&((const float4*)zblk)[(size_t)r * (DIMS / 4) + k4]);
        float4 qv = __ldg(&((const float4*)(emb + (size_t)idxs[r] * DIMS))[k4]);
        float4 ov; float d;
        d = __fsub_rn(qv.x, zv.x); ov.x = __fadd_rn(zv.x, d); lsum += (double)__fmul_rn(d, d);
        d = __fsub_rn(qv.y, zv.y); ov.y = __fadd_rn(zv.y, d); lsum += (double)__fmul_rn(d, d);
        d = __fsub_rn(qv.z, zv.z); ov.z = __fadd_rn(zv.z, d); lsum += (double)__fmul_rn(d, d);
        d = __fsub_rn(qv.w, zv.w); ov.w = __fadd_rn(zv.w, d); lsum += (double)__fmul_rn(d, d);
        ((float4*)outblk)[i] = ov;
    }
    red[tid] = lsum;
    __syncthreads();
    for (int s = 128; s > 0; s >>= 1) {
        if (tid < s) red[tid] += red[tid + s];
        __syncthreads();
    }
    if (tid == 0) atomicAdd(&g_loss_accum, red[0]);
}

// ---------------------------------------------------------------------------
__global__ void vq_finalize(float* __restrict__ out, int out_size) {
    double mean = g_loss_accum / (double)((size_t)NROWS * DIMS);
    float loss = (float)(0.5 * mean);
    out[out_size - 2] = loss;   // commitment_loss
    out[out_size - 1] = loss;   // emb_loss
}

// ---------------------------------------------------------------------------
extern "C" void kernel_launch(void* const* d_in, const int* in_sizes, int n_in,
                              void* d_out, int out_size) {
    const float* z   = (const float*)d_in[0];
    const float* emb = (const float*)d_in[1];
    if (n_in >= 2 && in_sizes[0] == NCODES * DIMS && in_sizes[1] == NROWS * DIMS) {
        emb = (const float*)d_in[0];
        z   = (const float*)d_in[1];
    }
    float* out = (float*)d_out;

    vq_prep<<<(NCODES * 32 + 255) / 256, 256>>>(emb);

    cudaFuncSetAttribute(vq_main, cudaFuncAttributeMaxDynamicSharedMemorySize,
                         SMEM_BYTES);
    vq_main<<<NROWS / TM, 256, SMEM_BYTES>>>(z, emb, out);

    vq_finalize<<<1, 1>>>(out, out_size);
}